// round 2
// baseline (speedup 1.0000x reference)
#include <cuda_runtime.h>
#include <cstdint>

#define S_LEN 2048
#define B_SZ  256
#define H_SZ  256
#define NI    128
#define NO    128

// Scratch (allocation-free): Zx laid out (t, b, h); H laid out (t, h, b)
__device__ float g_Zx[(size_t)S_LEN * B_SZ * H_SZ];
__device__ float g_H [(size_t)S_LEN * H_SZ * B_SZ];
__device__ unsigned g_bar;

__device__ __forceinline__ float gelu_f(float x) {
    return 0.5f * x * (1.0f + erff(x * 0.70710678118654752440f));
}

__global__ void init_kernel() { g_bar = 0u; }

// ---------------------------------------------------------------------------
// Kernel A: Zx[t,b,n] = sum_i X[b,t,i] * W_ih[n,i] + b_ih[n]
// GEMM M=S*B (row r = t*256+b), K=128, N=256. Tile 128x64, 256 thr, 8x4/thread
// ---------------------------------------------------------------------------
__global__ void __launch_bounds__(256) proj_in_kernel(
    const float* __restrict__ X, const float* __restrict__ W_ih,
    const float* __restrict__ b_ih)
{
    __shared__ float As[16][132];
    __shared__ float Bs[16][68];
    const int tid = threadIdx.x;
    const int r0  = blockIdx.x * 128;
    const int n0  = blockIdx.y * 64;
    const int t   = r0 >> 8;
    const int b0  = r0 & 255;
    const int tx  = tid & 15, ty = tid >> 4;

    float acc[8][4];
    #pragma unroll
    for (int i = 0; i < 8; ++i)
        #pragma unroll
        for (int j = 0; j < 4; ++j) acc[i][j] = 0.f;

    const int kq = (tid & 3) * 4;
    const int am = tid >> 2;

    for (int k0 = 0; k0 < NI; k0 += 16) {
        #pragma unroll
        for (int h = 0; h < 2; ++h) {
            const int m = am + h * 64;
            const float4 v = *(const float4*)(X + (size_t)(b0 + m) * (S_LEN * NI)
                                              + (size_t)t * NI + k0 + kq);
            As[kq + 0][m] = v.x; As[kq + 1][m] = v.y;
            As[kq + 2][m] = v.z; As[kq + 3][m] = v.w;
        }
        {
            const float4 v = *(const float4*)(W_ih + (size_t)(n0 + am) * 384 + k0 + kq);
            Bs[kq + 0][am] = v.x; Bs[kq + 1][am] = v.y;
            Bs[kq + 2][am] = v.z; Bs[kq + 3][am] = v.w;
        }
        __syncthreads();
        #pragma unroll
        for (int kk = 0; kk < 16; ++kk) {
            const float4 a0 = *(const float4*)&As[kk][ty * 8];
            const float4 a1 = *(const float4*)&As[kk][ty * 8 + 4];
            const float4 bv = *(const float4*)&Bs[kk][tx * 4];
            const float a[8] = {a0.x, a0.y, a0.z, a0.w, a1.x, a1.y, a1.z, a1.w};
            const float bb[4] = {bv.x, bv.y, bv.z, bv.w};
            #pragma unroll
            for (int i = 0; i < 8; ++i)
                #pragma unroll
                for (int j = 0; j < 4; ++j) acc[i][j] = fmaf(a[i], bb[j], acc[i][j]);
        }
        __syncthreads();
    }
    const float4 bv = *(const float4*)(b_ih + n0 + tx * 4);
    #pragma unroll
    for (int i = 0; i < 8; ++i) {
        float4 o;
        o.x = acc[i][0] + bv.x; o.y = acc[i][1] + bv.y;
        o.z = acc[i][2] + bv.z; o.w = acc[i][3] + bv.w;
        *(float4*)(g_Zx + (size_t)(r0 + ty * 8 + i) * 256 + n0 + tx * 4) = o;
    }
}

// ---------------------------------------------------------------------------
// Kernel B: persistent recurrence. 64 CTAs x 256 thr, 4 H-columns per CTA.
// Per step: z[:, cols] = Zx[t][:, cols] + h_prev @ W_h[:, cols];
// BN over batch (CTA-local), exact GELU, write h into g_H[t] (layout (h,b)).
// Global spin barrier per step (all 64 CTAs co-resident).
// ---------------------------------------------------------------------------
#define NCTA 64
#define NC   4
#define KC   16
#define NCH  (H_SZ / KC)

__device__ __forceinline__ void cp_async16(float* smem_dst, const float* gsrc) {
    unsigned s = (unsigned)__cvta_generic_to_shared(smem_dst);
    asm volatile("cp.async.cg.shared.global [%0], [%1], 16;\n" :: "r"(s), "l"(gsrc));
}
__device__ __forceinline__ void cp_async_wait_all_f() {
    asm volatile("cp.async.wait_all;\n" ::: "memory");
}

__global__ void __launch_bounds__(256, 1) rec_kernel(
    const float* __restrict__ W_ih, const float* __restrict__ gamma,
    const float* __restrict__ beta)
{
    __shared__ float T[2][KC][256];     // 32 KB, h chunks (k-major, b contiguous)
    __shared__ float Wsm[H_SZ][NC];     // 4 KB W_h slice
    __shared__ float red[16];
    __shared__ float stats[NC][2];
    __shared__ float gbs[NC][2];

    const int tid = threadIdx.x;
    const int c   = tid >> 6;            // 0..3 (column within CTA slice)
    const int r0  = (tid & 63) << 2;     // 4 consecutive batch rows
    const int c0  = blockIdx.x * NC;

    for (int i = tid; i < H_SZ * NC; i += 256) {
        const int cc = i & 3, k = i >> 2;
        Wsm[k][cc] = W_ih[(size_t)(c0 + cc) * 384 + NI + k];
    }
    if (tid < NC) { gbs[tid][0] = gamma[c0 + tid]; gbs[tid][1] = beta[c0 + tid]; }
    __syncthreads();

    for (int t = 0; t < S_LEN; ++t) {
        float a0 = 0.f, a1 = 0.f, a2 = 0.f, a3 = 0.f;
        if (t > 0) {
            const float* hp = g_H + (size_t)(t - 1) * 65536;
            #pragma unroll
            for (int i = 0; i < 4; ++i)
                cp_async16(&T[0][0][0] + (i * 256 + tid) * 4, hp + (i * 256 + tid) * 4);
            #pragma unroll 2
            for (int kc = 0; kc < NCH; ++kc) {
                cp_async_wait_all_f();
                __syncthreads();
                if (kc + 1 < NCH) {
                    const float* src = hp + (size_t)(kc + 1) * KC * 256;
                    float* dst = &T[(kc + 1) & 1][0][0];
                    #pragma unroll
                    for (int i = 0; i < 4; ++i)
                        cp_async16(dst + (i * 256 + tid) * 4, src + (i * 256 + tid) * 4);
                }
                const float* Tb = &T[kc & 1][0][0];
                const int kb = kc * KC;
                #pragma unroll
                for (int kk = 0; kk < KC; ++kk) {
                    const float4 hv = *(const float4*)(Tb + kk * 256 + r0);
                    const float w = Wsm[kb + kk][c];
                    a0 = fmaf(hv.x, w, a0); a1 = fmaf(hv.y, w, a1);
                    a2 = fmaf(hv.z, w, a2); a3 = fmaf(hv.w, w, a3);
                }
            }
        }
        // add Zx (layout (t,b,h))
        {
            const float* zx = g_Zx + (size_t)t * 65536 + c0 + c;
            a0 += zx[(size_t)(r0 + 0) * 256]; a1 += zx[(size_t)(r0 + 1) * 256];
            a2 += zx[(size_t)(r0 + 2) * 256]; a3 += zx[(size_t)(r0 + 3) * 256];
        }
        // BN stats over batch for this column (warps 2c, 2c+1 own it)
        float s = a0 + a1 + a2 + a3;
        float q = a0 * a0 + a1 * a1 + a2 * a2 + a3 * a3;
        #pragma unroll
        for (int off = 16; off; off >>= 1) {
            s += __shfl_xor_sync(0xffffffffu, s, off);
            q += __shfl_xor_sync(0xffffffffu, q, off);
        }
        const int w = tid >> 5;
        if ((tid & 31) == 0) { red[w * 2] = s; red[w * 2 + 1] = q; }
        __syncthreads();
        if (tid < NC) {
            const float ss = red[tid * 4 + 0] + red[tid * 4 + 2];
            const float qq = red[tid * 4 + 1] + red[tid * 4 + 3];
            const float mu = ss * (1.f / 256.f);
            const float var = fmaf(-mu, mu, qq * (1.f / 256.f));
            stats[tid][0] = mu;
            stats[tid][1] = rsqrtf(var + 1e-5f);
        }
        __syncthreads();
        const float mu = stats[c][0];
        const float sc = stats[c][1] * gbs[c][0];
        const float be = gbs[c][1];
        float4 o;
        o.x = gelu_f(fmaf(a0 - mu, sc, be));
        o.y = gelu_f(fmaf(a1 - mu, sc, be));
        o.z = gelu_f(fmaf(a2 - mu, sc, be));
        o.w = gelu_f(fmaf(a3 - mu, sc, be));
        *(float4*)(g_H + (size_t)t * 65536 + (size_t)(c0 + c) * 256 + r0) = o;
        // global step barrier
        __threadfence();
        __syncthreads();
        if (tid == 0) {
            atomicAdd(&g_bar, 1u);
            const unsigned tgt = (unsigned)NCTA * (unsigned)(t + 1);
            while (*((volatile unsigned*)&g_bar) < tgt) { }
        }
        __syncthreads();
    }
}

// ---------------------------------------------------------------------------
// Kernel C: out[b,t,n] = gelu( sum_k g_H[t,k,b] * W_ho[n,k] + b_ho[n] )
// GEMM M=S*B, K=256, N=128. Tile 128x64. A is K-major in g_H -> direct loads.
// ---------------------------------------------------------------------------
__global__ void __launch_bounds__(256) proj_out_kernel(
    const float* __restrict__ W_ho, const float* __restrict__ b_ho,
    float* __restrict__ out)
{
    __shared__ float As[16][128];
    __shared__ float Bs[16][68];
    const int tid = threadIdx.x;
    const int r0  = blockIdx.x * 128;
    const int n0  = blockIdx.y * 64;
    const int t   = r0 >> 8;
    const int b0  = r0 & 255;
    const int tx  = tid & 15, ty = tid >> 4;

    float acc[8][4];
    #pragma unroll
    for (int i = 0; i < 8; ++i)
        #pragma unroll
        for (int j = 0; j < 4; ++j) acc[i][j] = 0.f;

    const int kq = (tid & 3) * 4;
    const int bn = tid >> 2;
    const float* hbase = g_H + (size_t)t * 65536;

    for (int k0 = 0; k0 < H_SZ; k0 += 16) {
        #pragma unroll
        for (int p = 0; p < 2; ++p) {
            const int kk = p * 8 + (tid >> 5);
            const int bb = (tid & 31) * 4;
            *(float4*)&As[kk][bb] =
                *(const float4*)(hbase + (size_t)(k0 + kk) * 256 + b0 + bb);
        }
        {
            const float4 v = *(const float4*)(W_ho + (size_t)(n0 + bn) * H_SZ + k0 + kq);
            Bs[kq + 0][bn] = v.x; Bs[kq + 1][bn] = v.y;
            Bs[kq + 2][bn] = v.z; Bs[kq + 3][bn] = v.w;
        }
        __syncthreads();
        #pragma unroll
        for (int kk = 0; kk < 16; ++kk) {
            const float4 a0 = *(const float4*)&As[kk][ty * 8];
            const float4 a1 = *(const float4*)&As[kk][ty * 8 + 4];
            const float4 bv = *(const float4*)&Bs[kk][tx * 4];
            const float a[8] = {a0.x, a0.y, a0.z, a0.w, a1.x, a1.y, a1.z, a1.w};
            const float bb[4] = {bv.x, bv.y, bv.z, bv.w};
            #pragma unroll
            for (int i = 0; i < 8; ++i)
                #pragma unroll
                for (int j = 0; j < 4; ++j) acc[i][j] = fmaf(a[i], bb[j], acc[i][j]);
        }
        __syncthreads();
    }
    const float4 bv = *(const float4*)(b_ho + n0 + tx * 4);
    #pragma unroll
    for (int i = 0; i < 8; ++i) {
        float4 o;
        o.x = gelu_f(acc[i][0] + bv.x);
        o.y = gelu_f(acc[i][1] + bv.y);
        o.z = gelu_f(acc[i][2] + bv.z);
        o.w = gelu_f(acc[i][3] + bv.w);
        *(float4*)(out + (size_t)(b0 + ty * 8 + i) * (S_LEN * NO)
                   + (size_t)t * NO + n0 + tx * 4) = o;
    }
}

// ---------------------------------------------------------------------------
extern "C" void kernel_launch(void* const* d_in, const int* in_sizes, int n_in,
                              void* d_out, int out_size)
{
    const float* X     = (const float*)d_in[0];
    const float* W_ih  = (const float*)d_in[1];
    const float* b_ih  = (const float*)d_in[2];
    const float* W_ho  = (const float*)d_in[3];
    const float* b_ho  = (const float*)d_in[4];
    const float* gamma = (const float*)d_in[5];
    const float* beta  = (const float*)d_in[6];
    float* out = (float*)d_out;

    init_kernel<<<1, 1>>>();
    proj_in_kernel<<<dim3((S_LEN * B_SZ) / 128, H_SZ / 64), 256>>>(X, W_ih, b_ih);
    rec_kernel<<<NCTA, 256>>>(W_ih, gamma, beta);
    proj_out_kernel<<<dim3((S_LEN * B_SZ) / 128, NO / 64), 256>>>(W_ho, b_ho, out);
}

// round 4
// speedup vs baseline: 1.2218x; 1.2218x over previous
#include <cuda_runtime.h>
#include <cstdint>

#define S_LEN 2048
#define B_SZ  256
#define H_SZ  256
#define NI    128
#define NO    128

#define BG  32   // batch groups (8 rows each)
#define CGN 4    // col groups (64 cols each)

// Scratch (allocation-free)
__device__ float g_Zx[(size_t)S_LEN * B_SZ * H_SZ];          // (t, b, h)
__device__ float g_H [(size_t)S_LEN * H_SZ * B_SZ];          // (t, h, b)
__device__ float g_psum[2][H_SZ][BG];
__device__ float g_psq [2][H_SZ][BG];
__device__ unsigned g_cnt_stats[CGN * 32];                   // padded
__device__ unsigned g_cnt_h[BG * 32];                        // padded

__device__ __forceinline__ float gelu_f(float x) {
    return 0.5f * x * (1.0f + erff(x * 0.70710678118654752440f));
}

__global__ void init_kernel() {
    const int tid = threadIdx.x;
    for (int i = tid; i < CGN * 32; i += 256) g_cnt_stats[i] = 0u;
    for (int i = tid; i < BG * 32; i += 256) g_cnt_h[i] = 0u;
}

// ---------------------------------------------------------------------------
// Kernel A: Zx[t,b,n] = sum_i X[b,t,i] * W_ih[n,i] + b_ih[n]
// ---------------------------------------------------------------------------
__global__ void __launch_bounds__(256) proj_in_kernel(
    const float* __restrict__ X, const float* __restrict__ W_ih,
    const float* __restrict__ b_ih)
{
    __shared__ float As[16][132];
    __shared__ float Bs[16][68];
    const int tid = threadIdx.x;
    const int r0  = blockIdx.x * 128;
    const int n0  = blockIdx.y * 64;
    const int t   = r0 >> 8;
    const int b0  = r0 & 255;
    const int tx  = tid & 15, ty = tid >> 4;

    float acc[8][4];
    #pragma unroll
    for (int i = 0; i < 8; ++i)
        #pragma unroll
        for (int j = 0; j < 4; ++j) acc[i][j] = 0.f;

    const int kq = (tid & 3) * 4;
    const int am = tid >> 2;

    for (int k0 = 0; k0 < NI; k0 += 16) {
        #pragma unroll
        for (int h = 0; h < 2; ++h) {
            const int m = am + h * 64;
            const float4 v = *(const float4*)(X + (size_t)(b0 + m) * (S_LEN * NI)
                                              + (size_t)t * NI + k0 + kq);
            As[kq + 0][m] = v.x; As[kq + 1][m] = v.y;
            As[kq + 2][m] = v.z; As[kq + 3][m] = v.w;
        }
        {
            const float4 v = *(const float4*)(W_ih + (size_t)(n0 + am) * 384 + k0 + kq);
            Bs[kq + 0][am] = v.x; Bs[kq + 1][am] = v.y;
            Bs[kq + 2][am] = v.z; Bs[kq + 3][am] = v.w;
        }
        __syncthreads();
        #pragma unroll
        for (int kk = 0; kk < 16; ++kk) {
            const float4 a0 = *(const float4*)&As[kk][ty * 8];
            const float4 a1 = *(const float4*)&As[kk][ty * 8 + 4];
            const float4 bv = *(const float4*)&Bs[kk][tx * 4];
            const float a[8] = {a0.x, a0.y, a0.z, a0.w, a1.x, a1.y, a1.z, a1.w};
            const float bb[4] = {bv.x, bv.y, bv.z, bv.w};
            #pragma unroll
            for (int i = 0; i < 8; ++i)
                #pragma unroll
                for (int j = 0; j < 4; ++j) acc[i][j] = fmaf(a[i], bb[j], acc[i][j]);
        }
        __syncthreads();
    }
    const float4 bv = *(const float4*)(b_ih + n0 + tx * 4);
    #pragma unroll
    for (int i = 0; i < 8; ++i) {
        float4 o;
        o.x = acc[i][0] + bv.x; o.y = acc[i][1] + bv.y;
        o.z = acc[i][2] + bv.z; o.w = acc[i][3] + bv.w;
        *(float4*)(g_Zx + (size_t)(r0 + ty * 8 + i) * 256 + n0 + tx * 4) = o;
    }
}

// ---------------------------------------------------------------------------
// Kernel B: persistent recurrence. 128 CTAs = 32 batch-groups x 4 col-groups.
// W_h slice (256x64) lives in SMEM for the whole kernel. Per step the matvec
// is entirely SMEM-local; only BN partials + 8 h-rows cross CTAs.
// ---------------------------------------------------------------------------
struct RecSmem {
    float W[256][64];      // [k][col]           64 KB
    float h[8][256];       // [row][k]            8 KB
    float pssum[8][64];    // per-row col sums    2 KB
    float pssq [8][64];    //                     2 KB
    float trans[64][9];    // h transpose [col][row]+pad (9 = conflict padding)
    float stats[64][2];    // mu, rs*gamma
    float gb[64][2];       // gamma, beta
};

__device__ __forceinline__ float4 ldcg4(const float* p) {
    return __ldcg((const float4*)p);
}

__global__ void __launch_bounds__(256, 1) rec_kernel(
    const float* __restrict__ W_ih, const float* __restrict__ gamma,
    const float* __restrict__ beta)
{
    extern __shared__ char smem_raw[];
    RecSmem* s = (RecSmem*)smem_raw;

    const int tid  = threadIdx.x;
    const int bg   = blockIdx.x;     // 0..31
    const int cg   = blockIdx.y;     // 0..3
    const int row  = tid >> 5;       // 0..7
    const int lane = tid & 31;
    const int c    = lane * 2;       // 0..62

    // Load W slice: W[k][col] = W_ih[(cg*64+col)*384 + 128 + k]
    for (int i = tid; i < 256 * 64; i += 256) {
        const int cc = i & 63, k = i >> 6;
        s->W[k][cc] = W_ih[(size_t)(cg * 64 + cc) * 384 + NI + k];
    }
    if (tid < 64) {
        s->gb[tid][0] = gamma[cg * 64 + tid];
        s->gb[tid][1] = beta[cg * 64 + tid];
    }
    __syncthreads();

    volatile unsigned* vcnt_s = (volatile unsigned*)&g_cnt_stats[cg * 32];
    volatile unsigned* vcnt_h = (volatile unsigned*)&g_cnt_h[bg * 32];

    for (int t = 0; t < S_LEN; ++t) {
        float z0 = 0.f, z1 = 0.f;
        if (t > 0) {
            const float* hr = &s->h[row][0];
            #pragma unroll 4
            for (int k0 = 0; k0 < 256; k0 += 8) {
                const float4 hA = *(const float4*)(hr + k0);
                const float4 hB = *(const float4*)(hr + k0 + 4);
                const float2 w0 = *(const float2*)&s->W[k0 + 0][c];
                const float2 w1 = *(const float2*)&s->W[k0 + 1][c];
                const float2 w2 = *(const float2*)&s->W[k0 + 2][c];
                const float2 w3 = *(const float2*)&s->W[k0 + 3][c];
                const float2 w4 = *(const float2*)&s->W[k0 + 4][c];
                const float2 w5 = *(const float2*)&s->W[k0 + 5][c];
                const float2 w6 = *(const float2*)&s->W[k0 + 6][c];
                const float2 w7 = *(const float2*)&s->W[k0 + 7][c];
                z0 = fmaf(hA.x, w0.x, z0); z1 = fmaf(hA.x, w0.y, z1);
                z0 = fmaf(hA.y, w1.x, z0); z1 = fmaf(hA.y, w1.y, z1);
                z0 = fmaf(hA.z, w2.x, z0); z1 = fmaf(hA.z, w2.y, z1);
                z0 = fmaf(hA.w, w3.x, z0); z1 = fmaf(hA.w, w3.y, z1);
                z0 = fmaf(hB.x, w4.x, z0); z1 = fmaf(hB.x, w4.y, z1);
                z0 = fmaf(hB.y, w5.x, z0); z1 = fmaf(hB.y, w5.y, z1);
                z0 = fmaf(hB.z, w6.x, z0); z1 = fmaf(hB.z, w6.y, z1);
                z0 = fmaf(hB.w, w7.x, z0); z1 = fmaf(hB.w, w7.y, z1);
            }
        }
        // add Zx (layout (t,b,h))
        {
            const float2 zx = *(const float2*)(g_Zx + (size_t)t * 65536
                                + (size_t)(bg * 8 + row) * 256 + cg * 64 + c);
            z0 += zx.x; z1 += zx.y;
        }
        // per-row partials into smem
        *(float2*)&s->pssum[row][c] = make_float2(z0, z1);
        *(float2*)&s->pssq [row][c] = make_float2(z0 * z0, z1 * z1);
        __syncthreads();
        // reduce over 8 rows, write CTA partial to global (double-buffered)
        const int par = t & 1;
        if (tid < 64) {
            float v = 0.f;
            #pragma unroll
            for (int r = 0; r < 8; ++r) v += s->pssum[r][tid];
            g_psum[par][cg * 64 + tid][bg] = v;
        } else if (tid < 128) {
            const int cc = tid - 64;
            float v = 0.f;
            #pragma unroll
            for (int r = 0; r < 8; ++r) v += s->pssq[r][cc];
            g_psq[par][cg * 64 + cc][bg] = v;
        }
        __threadfence();
        __syncthreads();
        // stats sub-barrier: 32 CTAs of this col-group
        if (tid == 0) {
            atomicAdd(&g_cnt_stats[cg * 32], 1u);
            const unsigned tgt = 32u * (unsigned)(t + 1);
            while (*vcnt_s < tgt) { }
        }
        __syncthreads();
        // deterministic ordered reduction of 32 partials, fold gamma
        if (tid < 64) {
            const float* ps = &g_psum[par][cg * 64 + tid][0];
            const float* pq = &g_psq [par][cg * 64 + tid][0];
            float sm = 0.f, sq = 0.f;
            #pragma unroll
            for (int j = 0; j < 8; ++j) {
                const float4 a = ldcg4(ps + j * 4);
                const float4 b = ldcg4(pq + j * 4);
                sm += ((a.x + a.y) + (a.z + a.w));
                sq += ((b.x + b.y) + (b.z + b.w));
            }
            const float mu  = sm * (1.f / 256.f);
            const float var = fmaf(-mu, mu, sq * (1.f / 256.f));
            s->stats[tid][0] = mu;
            s->stats[tid][1] = rsqrtf(var + 1e-5f) * s->gb[tid][0];
        }
        __syncthreads();
        // normalize + GELU
        const float mu0 = s->stats[c][0],     k0s = s->stats[c][1];
        const float mu1 = s->stats[c + 1][0], k1s = s->stats[c + 1][1];
        const float h0 = gelu_f(fmaf(z0 - mu0, k0s, s->gb[c][1]));
        const float h1 = gelu_f(fmaf(z1 - mu1, k1s, s->gb[c + 1][1]));
        s->trans[c][row]     = h0;
        s->trans[c + 1][row] = h1;
        __syncthreads();
        // coalesced h write to g_H (t, col, b). trans rows are 36B-strided
        // (conflict padding), so gather with scalar LDS, store STG.128.
        if (tid < 128) {
            const int col = tid >> 1, p = tid & 1;
            float4 v;
            v.x = s->trans[col][p * 4 + 0];
            v.y = s->trans[col][p * 4 + 1];
            v.z = s->trans[col][p * 4 + 2];
            v.w = s->trans[col][p * 4 + 3];
            *(float4*)(g_H + (size_t)t * 65536 + (size_t)(cg * 64 + col) * 256
                       + bg * 8 + p * 4) = v;
        }
        __threadfence();
        __syncthreads();
        if (t + 1 < S_LEN) {
            // h-ready sub-barrier: 4 col-group CTAs of this batch-group
            if (tid == 0) {
                atomicAdd(&g_cnt_h[bg * 32], 1u);
                const unsigned tgt = 4u * (unsigned)(t + 1);
                while (*vcnt_h < tgt) { }
            }
            __syncthreads();
            // reload own 8 rows of full h (all 256 cols)
            const float* src = g_H + (size_t)t * 65536 + (size_t)tid * 256 + bg * 8;
            const float4 a = ldcg4(src);
            const float4 b = ldcg4(src + 4);
            s->h[0][tid] = a.x; s->h[1][tid] = a.y;
            s->h[2][tid] = a.z; s->h[3][tid] = a.w;
            s->h[4][tid] = b.x; s->h[5][tid] = b.y;
            s->h[6][tid] = b.z; s->h[7][tid] = b.w;
            __syncthreads();
        }
    }
}

// ---------------------------------------------------------------------------
// Kernel C: out[b,t,n] = gelu( sum_k g_H[t,k,b] * W_ho[n,k] + b_ho[n] )
// ---------------------------------------------------------------------------
__global__ void __launch_bounds__(256) proj_out_kernel(
    const float* __restrict__ W_ho, const float* __restrict__ b_ho,
    float* __restrict__ out)
{
    __shared__ float As[16][128];
    __shared__ float Bs[16][68];
    const int tid = threadIdx.x;
    const int r0  = blockIdx.x * 128;
    const int n0  = blockIdx.y * 64;
    const int t   = r0 >> 8;
    const int b0  = r0 & 255;
    const int tx  = tid & 15, ty = tid >> 4;

    float acc[8][4];
    #pragma unroll
    for (int i = 0; i < 8; ++i)
        #pragma unroll
        for (int j = 0; j < 4; ++j) acc[i][j] = 0.f;

    const int kq = (tid & 3) * 4;
    const int bn = tid >> 2;
    const float* hbase = g_H + (size_t)t * 65536;

    for (int k0 = 0; k0 < H_SZ; k0 += 16) {
        #pragma unroll
        for (int p = 0; p < 2; ++p) {
            const int kk = p * 8 + (tid >> 5);
            const int bb = (tid & 31) * 4;
            *(float4*)&As[kk][bb] =
                *(const float4*)(hbase + (size_t)(k0 + kk) * 256 + b0 + bb);
        }
        {
            const float4 v = *(const float4*)(W_ho + (size_t)(n0 + bn) * H_SZ + k0 + kq);
            Bs[kq + 0][bn] = v.x; Bs[kq + 1][bn] = v.y;
            Bs[kq + 2][bn] = v.z; Bs[kq + 3][bn] = v.w;
        }
        __syncthreads();
        #pragma unroll
        for (int kk = 0; kk < 16; ++kk) {
            const float4 a0 = *(const float4*)&As[kk][ty * 8];
            const float4 a1 = *(const float4*)&As[kk][ty * 8 + 4];
            const float4 bv = *(const float4*)&Bs[kk][tx * 4];
            const float a[8] = {a0.x, a0.y, a0.z, a0.w, a1.x, a1.y, a1.z, a1.w};
            const float bb[4] = {bv.x, bv.y, bv.z, bv.w};
            #pragma unroll
            for (int i = 0; i < 8; ++i)
                #pragma unroll
                for (int j = 0; j < 4; ++j) acc[i][j] = fmaf(a[i], bb[j], acc[i][j]);
        }
        __syncthreads();
    }
    const float4 bv = *(const float4*)(b_ho + n0 + tx * 4);
    #pragma unroll
    for (int i = 0; i < 8; ++i) {
        float4 o;
        o.x = gelu_f(acc[i][0] + bv.x);
        o.y = gelu_f(acc[i][1] + bv.y);
        o.z = gelu_f(acc[i][2] + bv.z);
        o.w = gelu_f(acc[i][3] + bv.w);
        *(float4*)(out + (size_t)(b0 + ty * 8 + i) * (S_LEN * NO)
                   + (size_t)t * NO + n0 + tx * 4) = o;
    }
}

// ---------------------------------------------------------------------------
extern "C" void kernel_launch(void* const* d_in, const int* in_sizes, int n_in,
                              void* d_out, int out_size)
{
    const float* X     = (const float*)d_in[0];
    const float* W_ih  = (const float*)d_in[1];
    const float* b_ih  = (const float*)d_in[2];
    const float* W_ho  = (const float*)d_in[3];
    const float* b_ho  = (const float*)d_in[4];
    const float* gamma = (const float*)d_in[5];
    const float* beta  = (const float*)d_in[6];
    float* out = (float*)d_out;

    // Idempotent, deterministic; not a stream op so it is not captured.
    cudaFuncSetAttribute(rec_kernel,
                         cudaFuncAttributeMaxDynamicSharedMemorySize,
                         (int)sizeof(RecSmem));

    init_kernel<<<1, 256>>>();
    proj_in_kernel<<<dim3((S_LEN * B_SZ) / 128, H_SZ / 64), 256>>>(X, W_ih, b_ih);
    rec_kernel<<<dim3(BG, CGN), 256, sizeof(RecSmem)>>>(W_ih, gamma, beta);
    proj_out_kernel<<<dim3((S_LEN * B_SZ) / 128, NO / 64), 256>>>(W_ho, b_ho, out);
}

// round 5
// speedup vs baseline: 1.3623x; 1.1150x over previous
#include <cuda_runtime.h>
#include <cstdint>

#define S_LEN 2048
#define B_SZ  256
#define H_SZ  256
#define NI    128
#define NO    128

#define BG  32   // batch groups (8 rows each)
#define CGN 4    // col groups (64 cols each)

typedef unsigned long long ull;

// Scratch (allocation-free)
__device__ float g_Zx[(size_t)S_LEN * B_SZ * H_SZ];          // (t, b, h)
__device__ float g_H [(size_t)S_LEN * H_SZ * B_SZ];          // (t, h, b)
__device__ float g_psum[2][H_SZ][BG];
__device__ float g_psq [2][H_SZ][BG];
__device__ unsigned g_cnt_stats[CGN * 32];                   // padded
__device__ unsigned g_cnt_h[BG * 32];                        // padded

__device__ __forceinline__ float gelu_f(float x) {
    return 0.5f * x * (1.0f + erff(x * 0.70710678118654752440f));
}

// ---- packed f32x2 helpers (sm_103a) ----
__device__ __forceinline__ void fma2(ull& d, ull a, ull b) {
    asm("fma.rn.f32x2 %0, %1, %2, %3;" : "=l"(d) : "l"(a), "l"(b), "l"(d));
}
__device__ __forceinline__ ull add2(ull a, ull b) {
    ull r; asm("add.rn.f32x2 %0, %1, %2;" : "=l"(r) : "l"(a), "l"(b)); return r;
}
__device__ __forceinline__ ull pack2(float x, float y) {
    ull r; asm("mov.b64 %0, {%1, %2};" : "=l"(r) : "f"(x), "f"(y)); return r;
}
__device__ __forceinline__ float2 unpack2(ull v) {
    float2 f; asm("mov.b64 {%0, %1}, %2;" : "=f"(f.x), "=f"(f.y) : "l"(v)); return f;
}

__global__ void init_kernel() {
    const int tid = threadIdx.x;
    for (int i = tid; i < CGN * 32; i += 256) g_cnt_stats[i] = 0u;
    for (int i = tid; i < BG * 32; i += 256) g_cnt_h[i] = 0u;
}

// ---------------------------------------------------------------------------
// Kernel A: Zx[t,b,n] = sum_i X[b,t,i] * W_ih[n,i] + b_ih[n]
// 128x128 tile, 256 threads, 8x8 outputs/thread via f32x2.
// ---------------------------------------------------------------------------
__global__ void __launch_bounds__(256) proj_in_kernel(
    const float* __restrict__ X, const float* __restrict__ W_ih,
    const float* __restrict__ b_ih)
{
    __shared__ float As[16][132];   // [kk][m]
    __shared__ float Bs[16][132];   // [kk][n]
    const int tid = threadIdx.x;
    const int r0  = blockIdx.x * 128;
    const int n0  = blockIdx.y * 128;
    const int t   = r0 >> 8;
    const int b0  = r0 & 255;
    const int tx  = tid & 15, ty = tid >> 4;

    ull acc[8][4];
    #pragma unroll
    for (int i = 0; i < 8; ++i)
        #pragma unroll
        for (int j = 0; j < 4; ++j) acc[i][j] = 0ull;

    const int am = tid >> 1, akq = (tid & 1) * 8;
    const int bn = tid & 127, bkq = (tid >> 7) * 8;

    for (int k0 = 0; k0 < NI; k0 += 16) {
        {
            const float* xp = X + (size_t)(b0 + am) * (S_LEN * NI)
                              + (size_t)t * NI + k0 + akq;
            const float4 v0 = *(const float4*)xp;
            const float4 v1 = *(const float4*)(xp + 4);
            As[akq + 0][am] = v0.x; As[akq + 1][am] = v0.y;
            As[akq + 2][am] = v0.z; As[akq + 3][am] = v0.w;
            As[akq + 4][am] = v1.x; As[akq + 5][am] = v1.y;
            As[akq + 6][am] = v1.z; As[akq + 7][am] = v1.w;
        }
        {
            const float* wp = W_ih + (size_t)(n0 + bn) * 384 + k0 + bkq;
            const float4 v0 = *(const float4*)wp;
            const float4 v1 = *(const float4*)(wp + 4);
            Bs[bkq + 0][bn] = v0.x; Bs[bkq + 1][bn] = v0.y;
            Bs[bkq + 2][bn] = v0.z; Bs[bkq + 3][bn] = v0.w;
            Bs[bkq + 4][bn] = v1.x; Bs[bkq + 5][bn] = v1.y;
            Bs[bkq + 6][bn] = v1.z; Bs[bkq + 7][bn] = v1.w;
        }
        __syncthreads();
        #pragma unroll
        for (int kk = 0; kk < 16; ++kk) {
            const float4 af0 = *(const float4*)&As[kk][ty * 8];
            const float4 af1 = *(const float4*)&As[kk][ty * 8 + 4];
            const ulonglong2 bp0 = *(const ulonglong2*)&Bs[kk][tx * 8];
            const ulonglong2 bp1 = *(const ulonglong2*)&Bs[kk][tx * 8 + 4];
            const float a[8] = {af0.x, af0.y, af0.z, af0.w,
                                af1.x, af1.y, af1.z, af1.w};
            #pragma unroll
            for (int i = 0; i < 8; ++i) {
                const ull aa = pack2(a[i], a[i]);
                fma2(acc[i][0], aa, bp0.x);
                fma2(acc[i][1], aa, bp0.y);
                fma2(acc[i][2], aa, bp1.x);
                fma2(acc[i][3], aa, bp1.y);
            }
        }
        __syncthreads();
    }
    const float4 bv0 = *(const float4*)(b_ih + n0 + tx * 8);
    const float4 bv1 = *(const float4*)(b_ih + n0 + tx * 8 + 4);
    #pragma unroll
    for (int i = 0; i < 8; ++i) {
        const float2 p0 = unpack2(acc[i][0]);
        const float2 p1 = unpack2(acc[i][1]);
        const float2 p2 = unpack2(acc[i][2]);
        const float2 p3 = unpack2(acc[i][3]);
        float* dst = g_Zx + (size_t)(r0 + ty * 8 + i) * 256 + n0 + tx * 8;
        float4 o0, o1;
        o0.x = p0.x + bv0.x; o0.y = p0.y + bv0.y;
        o0.z = p1.x + bv0.z; o0.w = p1.y + bv0.w;
        o1.x = p2.x + bv1.x; o1.y = p2.y + bv1.y;
        o1.z = p3.x + bv1.z; o1.w = p3.y + bv1.w;
        *(float4*)dst = o0;
        *(float4*)(dst + 4) = o1;
    }
}

// ---------------------------------------------------------------------------
// Kernel B: persistent recurrence. 128 CTAs = 32 bg x 4 cg.
// Warp = k-slice (32 k), thread = 8 rows x 2 cols (f32x2). W read once/step.
// ---------------------------------------------------------------------------
struct RecSmem {
    float  W[256][64];       // [k][col]                 64 KB
    float  h2[256][20];      // [k][{h_r,h_r} x8 + pad]  20 KB (80B stride)
    float2 part[8][8][32];   // [warp][row][lane]        16 KB
    float  pssum[8][64];
    float  pssq [8][64];
    float  trans[64][9];
    float  stats[64][2];
    float  gb[64][2];
};

__device__ __forceinline__ float4 ldcg4(const float* p) {
    return __ldcg((const float4*)p);
}

__global__ void __launch_bounds__(256, 1) rec_kernel(
    const float* __restrict__ W_ih, const float* __restrict__ gamma,
    const float* __restrict__ beta)
{
    extern __shared__ char smem_raw[];
    RecSmem* s = (RecSmem*)smem_raw;

    const int tid  = threadIdx.x;
    const int bg   = blockIdx.x;     // 0..31
    const int cg   = blockIdx.y;     // 0..3
    const int w    = tid >> 5;       // warp = k-slice
    const int lane = tid & 31;
    const int row  = w;              // for finalize phase: row 0..7
    const int c    = lane * 2;       // col pair 0..62

    for (int i = tid; i < 256 * 64; i += 256) {
        const int cc = i & 63, k = i >> 6;
        s->W[k][cc] = W_ih[(size_t)(cg * 64 + cc) * 384 + NI + k];
    }
    if (tid < 64) {
        s->gb[tid][0] = gamma[cg * 64 + tid];
        s->gb[tid][1] = beta[cg * 64 + tid];
    }
    __syncthreads();

    volatile unsigned* vcnt_s = (volatile unsigned*)&g_cnt_stats[cg * 32];
    volatile unsigned* vcnt_h = (volatile unsigned*)&g_cnt_h[bg * 32];

    for (int t = 0; t < S_LEN; ++t) {
        // prefetch Zx for this thread's finalize slot (t, bg*8+row, cg*64+c)
        const float2 zx = __ldcg((const float2*)(g_Zx + (size_t)t * 65536
                            + (size_t)(bg * 8 + row) * 256 + cg * 64 + c));

        ull acc[8];
        #pragma unroll
        for (int r = 0; r < 8; ++r) acc[r] = 0ull;

        if (t > 0) {
            const int kbeg = w * 32;
            #pragma unroll 4
            for (int k = kbeg; k < kbeg + 32; ++k) {
                const ull wv = *(const ull*)&s->W[k][c];
                const ulonglong2* hp = (const ulonglong2*)&s->h2[k][0];
                const ulonglong2 h01 = hp[0];
                const ulonglong2 h23 = hp[1];
                const ulonglong2 h45 = hp[2];
                const ulonglong2 h67 = hp[3];
                fma2(acc[0], h01.x, wv); fma2(acc[1], h01.y, wv);
                fma2(acc[2], h23.x, wv); fma2(acc[3], h23.y, wv);
                fma2(acc[4], h45.x, wv); fma2(acc[5], h45.y, wv);
                fma2(acc[6], h67.x, wv); fma2(acc[7], h67.y, wv);
            }
        }
        // cross-warp reduction buffer
        #pragma unroll
        for (int r = 0; r < 8; ++r) s->part[w][r][lane] = unpack2(acc[r]);
        __syncthreads();

        ull z2 = 0ull;
        #pragma unroll
        for (int w2 = 0; w2 < 8; ++w2) {
            const float2 p = s->part[w2][row][lane];
            z2 = add2(z2, pack2(p.x, p.y));
        }
        z2 = add2(z2, pack2(zx.x, zx.y));
        const float2 zf = unpack2(z2);
        const float z0 = zf.x, z1 = zf.y;

        // per-row partials for BN
        *(float2*)&s->pssum[row][c] = make_float2(z0, z1);
        *(float2*)&s->pssq [row][c] = make_float2(z0 * z0, z1 * z1);
        __syncthreads();

        const int par = t & 1;
        if (tid < 64) {
            float v = 0.f;
            #pragma unroll
            for (int r = 0; r < 8; ++r) v += s->pssum[r][tid];
            g_psum[par][cg * 64 + tid][bg] = v;
        } else if (tid < 128) {
            const int cc = tid - 64;
            float v = 0.f;
            #pragma unroll
            for (int r = 0; r < 8; ++r) v += s->pssq[r][cc];
            g_psq[par][cg * 64 + cc][bg] = v;
        }
        __threadfence();
        __syncthreads();
        if (tid == 0) {
            atomicAdd(&g_cnt_stats[cg * 32], 1u);
            const unsigned tgt = 32u * (unsigned)(t + 1);
            while (*vcnt_s < tgt) { }
        }
        __syncthreads();
        if (tid < 64) {
            const float* ps = &g_psum[par][cg * 64 + tid][0];
            const float* pq = &g_psq [par][cg * 64 + tid][0];
            float sm = 0.f, sq = 0.f;
            #pragma unroll
            for (int j = 0; j < 8; ++j) {
                const float4 a = ldcg4(ps + j * 4);
                const float4 b = ldcg4(pq + j * 4);
                sm += ((a.x + a.y) + (a.z + a.w));
                sq += ((b.x + b.y) + (b.z + b.w));
            }
            const float mu  = sm * (1.f / 256.f);
            const float var = fmaf(-mu, mu, sq * (1.f / 256.f));
            s->stats[tid][0] = mu;
            s->stats[tid][1] = rsqrtf(var + 1e-5f) * s->gb[tid][0];
        }
        __syncthreads();
        const float mu0 = s->stats[c][0],     k0s = s->stats[c][1];
        const float mu1 = s->stats[c + 1][0], k1s = s->stats[c + 1][1];
        const float h0 = gelu_f(fmaf(z0 - mu0, k0s, s->gb[c][1]));
        const float h1 = gelu_f(fmaf(z1 - mu1, k1s, s->gb[c + 1][1]));
        s->trans[c][row]     = h0;
        s->trans[c + 1][row] = h1;
        __syncthreads();
        if (tid < 128) {
            const int col = tid >> 1, p = tid & 1;
            float4 v;
            v.x = s->trans[col][p * 4 + 0];
            v.y = s->trans[col][p * 4 + 1];
            v.z = s->trans[col][p * 4 + 2];
            v.w = s->trans[col][p * 4 + 3];
            *(float4*)(g_H + (size_t)t * 65536 + (size_t)(cg * 64 + col) * 256
                       + bg * 8 + p * 4) = v;
        }
        __threadfence();
        __syncthreads();
        if (t + 1 < S_LEN) {
            if (tid == 0) {
                atomicAdd(&g_cnt_h[bg * 32], 1u);
                const unsigned tgt = 4u * (unsigned)(t + 1);
                while (*vcnt_h < tgt) { }
            }
            __syncthreads();
            // reload full h (col = tid), store duplicated pairs into h2
            const float* src = g_H + (size_t)t * 65536 + (size_t)tid * 256 + bg * 8;
            const float4 a = ldcg4(src);
            const float4 b = ldcg4(src + 4);
            float4* hrow = (float4*)&s->h2[tid][0];
            hrow[0] = make_float4(a.x, a.x, a.y, a.y);
            hrow[1] = make_float4(a.z, a.z, a.w, a.w);
            hrow[2] = make_float4(b.x, b.x, b.y, b.y);
            hrow[3] = make_float4(b.z, b.z, b.w, b.w);
            __syncthreads();
        }
    }
}

// ---------------------------------------------------------------------------
// Kernel C: out[b,t,n] = gelu( sum_k g_H[t,k,b] * W_ho[n,k] + b_ho[n] )
// 128x128 tile with f32x2.
// ---------------------------------------------------------------------------
__global__ void __launch_bounds__(256) proj_out_kernel(
    const float* __restrict__ W_ho, const float* __restrict__ b_ho,
    float* __restrict__ out)
{
    __shared__ float As[16][132];
    __shared__ float Bs[16][132];
    const int tid = threadIdx.x;
    const int r0  = blockIdx.x * 128;
    const int t   = r0 >> 8;
    const int b0  = r0 & 255;
    const int tx  = tid & 15, ty = tid >> 4;

    ull acc[8][4];
    #pragma unroll
    for (int i = 0; i < 8; ++i)
        #pragma unroll
        for (int j = 0; j < 4; ++j) acc[i][j] = 0ull;

    const int akk = tid >> 4, am16 = (tid & 15) * 8;
    const int bn = tid & 127, bkq = (tid >> 7) * 8;
    const float* hbase = g_H + (size_t)t * 65536;

    for (int k0 = 0; k0 < H_SZ; k0 += 16) {
        {
            const float* hp = hbase + (size_t)(k0 + akk) * 256 + b0 + am16;
            const float4 v0 = *(const float4*)hp;
            const float4 v1 = *(const float4*)(hp + 4);
            *(float4*)&As[akk][am16] = v0;
            *(float4*)&As[akk][am16 + 4] = v1;
        }
        {
            const float* wp = W_ho + (size_t)bn * H_SZ + k0 + bkq;
            const float4 v0 = *(const float4*)wp;
            const float4 v1 = *(const float4*)(wp + 4);
            Bs[bkq + 0][bn] = v0.x; Bs[bkq + 1][bn] = v0.y;
            Bs[bkq + 2][bn] = v0.z; Bs[bkq + 3][bn] = v0.w;
            Bs[bkq + 4][bn] = v1.x; Bs[bkq + 5][bn] = v1.y;
            Bs[bkq + 6][bn] = v1.z; Bs[bkq + 7][bn] = v1.w;
        }
        __syncthreads();
        #pragma unroll
        for (int kk = 0; kk < 16; ++kk) {
            const float4 af0 = *(const float4*)&As[kk][ty * 8];
            const float4 af1 = *(const float4*)&As[kk][ty * 8 + 4];
            const ulonglong2 bp0 = *(const ulonglong2*)&Bs[kk][tx * 8];
            const ulonglong2 bp1 = *(const ulonglong2*)&Bs[kk][tx * 8 + 4];
            const float a[8] = {af0.x, af0.y, af0.z, af0.w,
                                af1.x, af1.y, af1.z, af1.w};
            #pragma unroll
            for (int i = 0; i < 8; ++i) {
                const ull aa = pack2(a[i], a[i]);
                fma2(acc[i][0], aa, bp0.x);
                fma2(acc[i][1], aa, bp0.y);
                fma2(acc[i][2], aa, bp1.x);
                fma2(acc[i][3], aa, bp1.y);
            }
        }
        __syncthreads();
    }
    const float4 bv0 = *(const float4*)(b_ho + tx * 8);
    const float4 bv1 = *(const float4*)(b_ho + tx * 8 + 4);
    #pragma unroll
    for (int i = 0; i < 8; ++i) {
        const float2 p0 = unpack2(acc[i][0]);
        const float2 p1 = unpack2(acc[i][1]);
        const float2 p2 = unpack2(acc[i][2]);
        const float2 p3 = unpack2(acc[i][3]);
        float4 o0, o1;
        o0.x = gelu_f(p0.x + bv0.x); o0.y = gelu_f(p0.y + bv0.y);
        o0.z = gelu_f(p1.x + bv0.z); o0.w = gelu_f(p1.y + bv0.w);
        o1.x = gelu_f(p2.x + bv1.x); o1.y = gelu_f(p2.y + bv1.y);
        o1.z = gelu_f(p3.x + bv1.z); o1.w = gelu_f(p3.y + bv1.w);
        float* dst = out + (size_t)(b0 + ty * 8 + i) * (S_LEN * NO)
                     + (size_t)t * NO + tx * 8;
        *(float4*)dst = o0;
        *(float4*)(dst + 4) = o1;
    }
}

// ---------------------------------------------------------------------------
extern "C" void kernel_launch(void* const* d_in, const int* in_sizes, int n_in,
                              void* d_out, int out_size)
{
    const float* X     = (const float*)d_in[0];
    const float* W_ih  = (const float*)d_in[1];
    const float* b_ih  = (const float*)d_in[2];
    const float* W_ho  = (const float*)d_in[3];
    const float* b_ho  = (const float*)d_in[4];
    const float* gamma = (const float*)d_in[5];
    const float* beta  = (const float*)d_in[6];
    float* out = (float*)d_out;

    cudaFuncSetAttribute(rec_kernel,
                         cudaFuncAttributeMaxDynamicSharedMemorySize,
                         (int)sizeof(RecSmem));

    init_kernel<<<1, 256>>>();
    proj_in_kernel<<<dim3((S_LEN * B_SZ) / 128, H_SZ / 128), 256>>>(X, W_ih, b_ih);
    rec_kernel<<<dim3(BG, CGN), 256, sizeof(RecSmem)>>>(W_ih, gamma, beta);
    proj_out_kernel<<<(S_LEN * B_SZ) / 128, 256>>>(W_ho, b_ho, out);
}

// round 6
// speedup vs baseline: 1.9578x; 1.4371x over previous
#include <cuda_runtime.h>
#include <cstdint>

#define S_LEN 2048
#define B_SZ  256
#define H_SZ  256
#define NI    128
#define NO    128

typedef unsigned long long ull;

// Scratch (allocation-free)
__device__ float g_Zx[(size_t)S_LEN * B_SZ * H_SZ];   // (t, b, h)
__device__ float g_H [(size_t)S_LEN * B_SZ * H_SZ];   // (t, b, k)
__device__ float g_sum[S_LEN][H_SZ];                  // per-step BN sum (RED)
__device__ float g_sq [S_LEN][H_SZ];                  // per-step BN sumsq (RED)
__device__ unsigned g_cnt[32];                        // padded step counter

__device__ __forceinline__ float gelu_f(float x) {
    return 0.5f * x * (1.0f + erff(x * 0.70710678118654752440f));
}

// ---- packed f32x2 helpers (sm_103a) ----
__device__ __forceinline__ void fma2(ull& d, ull a, ull b) {
    asm("fma.rn.f32x2 %0, %1, %2, %3;" : "=l"(d) : "l"(a), "l"(b), "l"(d));
}
__device__ __forceinline__ ull add2(ull a, ull b) {
    ull r; asm("add.rn.f32x2 %0, %1, %2;" : "=l"(r) : "l"(a), "l"(b)); return r;
}
__device__ __forceinline__ ull pack2(float x, float y) {
    ull r; asm("mov.b64 %0, {%1, %2};" : "=l"(r) : "f"(x), "f"(y)); return r;
}
__device__ __forceinline__ float2 unpack2(ull v) {
    float2 f; asm("mov.b64 {%0, %1}, %2;" : "=f"(f.x), "=f"(f.y) : "l"(v)); return f;
}

// ---- cluster helpers ----
__device__ __forceinline__ unsigned ctarank() {
    unsigned r; asm("mov.u32 %0, %%cluster_ctarank;" : "=r"(r)); return r;
}
__device__ __forceinline__ unsigned smem_u32(const void* p) {
    return (unsigned)__cvta_generic_to_shared(p);
}
__device__ __forceinline__ unsigned mapa_peer(unsigned laddr, unsigned rank) {
    unsigned r;
    asm("mapa.shared::cluster.u32 %0, %1, %2;" : "=r"(r) : "r"(laddr), "r"(rank));
    return r;
}
__device__ __forceinline__ void st_cluster_f2(unsigned addr, float x, float y) {
    asm volatile("st.shared::cluster.v2.f32 [%0], {%1, %2};"
                 :: "r"(addr), "f"(x), "f"(y) : "memory");
}
__device__ __forceinline__ void cluster_sync_() {
    asm volatile("barrier.cluster.arrive.aligned;" ::: "memory");
    asm volatile("barrier.cluster.wait.aligned;" ::: "memory");
}
__device__ __forceinline__ void red_addf(float* p, float v) {
    asm volatile("red.global.add.f32 [%0], %1;" :: "l"(p), "f"(v) : "memory");
}

__global__ void init_kernel() {
    const size_t n = (size_t)S_LEN * H_SZ;
    const size_t stride = (size_t)gridDim.x * blockDim.x;
    for (size_t i = (size_t)blockIdx.x * blockDim.x + threadIdx.x; i < n; i += stride) {
        ((float*)g_sum)[i] = 0.f;
        ((float*)g_sq)[i]  = 0.f;
    }
    if (blockIdx.x == 0 && threadIdx.x < 32) g_cnt[threadIdx.x] = 0u;
}

// ---------------------------------------------------------------------------
// Kernel A: Zx[t,b,n] = sum_i X[b,t,i] * W_ih[n,i] + b_ih[n]  (R4 version)
// ---------------------------------------------------------------------------
__global__ void __launch_bounds__(256) proj_in_kernel(
    const float* __restrict__ X, const float* __restrict__ W_ih,
    const float* __restrict__ b_ih)
{
    __shared__ float As[16][132];
    __shared__ float Bs[16][68];
    const int tid = threadIdx.x;
    const int r0  = blockIdx.x * 128;
    const int n0  = blockIdx.y * 64;
    const int t   = r0 >> 8;
    const int b0  = r0 & 255;
    const int tx  = tid & 15, ty = tid >> 4;

    float acc[8][4];
    #pragma unroll
    for (int i = 0; i < 8; ++i)
        #pragma unroll
        for (int j = 0; j < 4; ++j) acc[i][j] = 0.f;

    const int kq = (tid & 3) * 4;
    const int am = tid >> 2;

    for (int k0 = 0; k0 < NI; k0 += 16) {
        #pragma unroll
        for (int h = 0; h < 2; ++h) {
            const int m = am + h * 64;
            const float4 v = *(const float4*)(X + (size_t)(b0 + m) * (S_LEN * NI)
                                              + (size_t)t * NI + k0 + kq);
            As[kq + 0][m] = v.x; As[kq + 1][m] = v.y;
            As[kq + 2][m] = v.z; As[kq + 3][m] = v.w;
        }
        {
            const float4 v = *(const float4*)(W_ih + (size_t)(n0 + am) * 384 + k0 + kq);
            Bs[kq + 0][am] = v.x; Bs[kq + 1][am] = v.y;
            Bs[kq + 2][am] = v.z; Bs[kq + 3][am] = v.w;
        }
        __syncthreads();
        #pragma unroll
        for (int kk = 0; kk < 16; ++kk) {
            const float4 a0 = *(const float4*)&As[kk][ty * 8];
            const float4 a1 = *(const float4*)&As[kk][ty * 8 + 4];
            const float4 bv = *(const float4*)&Bs[kk][tx * 4];
            const float a[8] = {a0.x, a0.y, a0.z, a0.w, a1.x, a1.y, a1.z, a1.w};
            const float bb[4] = {bv.x, bv.y, bv.z, bv.w};
            #pragma unroll
            for (int i = 0; i < 8; ++i)
                #pragma unroll
                for (int j = 0; j < 4; ++j) acc[i][j] = fmaf(a[i], bb[j], acc[i][j]);
        }
        __syncthreads();
    }
    const float4 bv = *(const float4*)(b_ih + n0 + tx * 4);
    #pragma unroll
    for (int i = 0; i < 8; ++i) {
        float4 o;
        o.x = acc[i][0] + bv.x; o.y = acc[i][1] + bv.y;
        o.z = acc[i][2] + bv.z; o.w = acc[i][3] + bv.w;
        *(float4*)(g_Zx + (size_t)(r0 + ty * 8 + i) * 256 + n0 + tx * 4) = o;
    }
}

// ---------------------------------------------------------------------------
// Kernel B: clustered recurrence. 64 clusters x 2 CTAs. Cluster owns 4 batch
// rows (all 256 cols); CTA owns a 128-k half of W_h IN REGISTERS (64 ull).
// Per step: reg matvec -> intra-CTA pair reduce -> DSMEM exchange +
// cluster.sync -> BN partials via red.f32 -> ONE 64-arrival counter barrier ->
// read 2KB stats -> gelu -> h stays in smem. h also STG'd to g_H (t,b,k).
// ---------------------------------------------------------------------------
__global__ void __launch_bounds__(256, 1) __cluster_dims__(2, 1, 1)
rec_kernel(const float* __restrict__ W_ih, const float* __restrict__ gamma,
           const float* __restrict__ beta)
{
    __shared__ float  h2[128][8];         // own k-half h, duplicated pairs (4 KB)
    __shared__ float2 redb[4][128];       // kq=1 partials (4 KB)
    __shared__ float2 zbuf[2][4][128];    // peer partials, parity-buffered (8 KB)

    const int tid  = threadIdx.x;
    const unsigned rank = ctarank();
    const int b0   = (blockIdx.x >> 1) * 4;
    const int kq   = tid >> 7;            // 0..1: 64-k quarter of global k
    const int cp   = tid & 127;           // column pair
    const int c    = cp * 2;

    // W half in registers: wreg[i] = {W[gk][c], W[gk][c+1]}, gk = rank*128+kq*64+i
    ull wreg[64];
    {
        const int kbase = NI + (int)rank * 128 + kq * 64;
        #pragma unroll
        for (int i = 0; i < 64; ++i) {
            const float w0 = W_ih[(size_t)(c    ) * 384 + kbase + i];
            const float w1 = W_ih[(size_t)(c + 1) * 384 + kbase + i];
            wreg[i] = pack2(w0, w1);
        }
    }
    const float gam0 = gamma[c], gam1 = gamma[c + 1];
    const float bet0 = beta[c],  bet1 = beta[c + 1];

    volatile unsigned* vcnt = (volatile unsigned*)&g_cnt[0];

    for (int t = 0; t < S_LEN; ++t) {
        // prefetch Zx (t,b,h): 4 rows x col pair
        float2 zx[4];
        if (kq == 0) {
            #pragma unroll
            for (int r = 0; r < 4; ++r)
                zx[r] = __ldcg((const float2*)(g_Zx
                          + ((size_t)t * 256 + b0 + r) * 256 + c));
        }

        ull acc[4] = {0ull, 0ull, 0ull, 0ull};
        if (t > 0) {
            const int kb = kq * 64;
            #pragma unroll
            for (int i = 0; i < 64; ++i) {
                const ulonglong2 p01 = *(const ulonglong2*)&h2[kb + i][0];
                const ulonglong2 p23 = *(const ulonglong2*)&h2[kb + i][4];
                fma2(acc[0], p01.x, wreg[i]);
                fma2(acc[1], p01.y, wreg[i]);
                fma2(acc[2], p23.x, wreg[i]);
                fma2(acc[3], p23.y, wreg[i]);
            }
            if (kq == 1) {
                #pragma unroll
                for (int r = 0; r < 4; ++r) redb[r][cp] = unpack2(acc[r]);
            }
        }
        __syncthreads();

        if (t > 0) {
            if (kq == 0) {
                #pragma unroll
                for (int r = 0; r < 4; ++r) {
                    const float2 p = redb[r][cp];
                    acc[r] = add2(acc[r], pack2(p.x, p.y));
                }
                // push own-k-half partial into peer's zbuf (parity t&1)
                #pragma unroll
                for (int r = 0; r < 4; ++r) {
                    const float2 v = unpack2(acc[r]);
                    const unsigned la = smem_u32(&zbuf[t & 1][r][cp]);
                    st_cluster_f2(mapa_peer(la, rank ^ 1u), v.x, v.y);
                }
            }
            cluster_sync_();   // all threads, both CTAs (uniform: t same everywhere)
        }

        float z[4][2];
        if (kq == 0) {
            #pragma unroll
            for (int r = 0; r < 4; ++r) {
                if (t > 0) {
                    const float2 p = zbuf[t & 1][r][cp];
                    acc[r] = add2(acc[r], pack2(p.x, p.y));
                }
                acc[r] = add2(acc[r], pack2(zx[r].x, zx[r].y));
                const float2 f = unpack2(acc[r]);
                z[r][0] = f.x; z[r][1] = f.y;
            }
            if (rank == 0) {
                const float s0 = (z[0][0] + z[1][0]) + (z[2][0] + z[3][0]);
                const float s1 = (z[0][1] + z[1][1]) + (z[2][1] + z[3][1]);
                const float q0 = (z[0][0]*z[0][0] + z[1][0]*z[1][0])
                               + (z[2][0]*z[2][0] + z[3][0]*z[3][0]);
                const float q1 = (z[0][1]*z[0][1] + z[1][1]*z[1][1])
                               + (z[2][1]*z[2][1] + z[3][1]*z[3][1]);
                red_addf(&g_sum[t][c],     s0);
                red_addf(&g_sum[t][c + 1], s1);
                red_addf(&g_sq [t][c],     q0);
                red_addf(&g_sq [t][c + 1], q1);
            }
        }
        __threadfence();
        __syncthreads();
        if (tid == 0) {
            if (rank == 0) atomicAdd(&g_cnt[0], 1u);
            const unsigned tgt = 64u * (unsigned)(t + 1);
            while (*vcnt < tgt) { }
            __threadfence();
        }
        __syncthreads();

        if (kq == 0) {
            const float2 sm = __ldcg((const float2*)&g_sum[t][c]);
            const float2 sq = __ldcg((const float2*)&g_sq[t][c]);
            const float mu0 = sm.x * (1.f / 256.f);
            const float mu1 = sm.y * (1.f / 256.f);
            const float v0  = fmaf(-mu0, mu0, sq.x * (1.f / 256.f));
            const float v1  = fmaf(-mu1, mu1, sq.y * (1.f / 256.f));
            const float k0  = rsqrtf(v0 + 1e-5f) * gam0;
            const float k1  = rsqrtf(v1 + 1e-5f) * gam1;
            float hv[4][2];
            #pragma unroll
            for (int r = 0; r < 4; ++r) {
                hv[r][0] = gelu_f(fmaf(z[r][0] - mu0, k0, bet0));
                hv[r][1] = gelu_f(fmaf(z[r][1] - mu1, k1, bet1));
            }
            // store into own h2 if this col pair is in our k-half
            if ((cp >> 6) == (int)rank) {
                const int kl = (cp & 63) * 2;
                *(float4*)&h2[kl][0]     = make_float4(hv[0][0], hv[0][0], hv[1][0], hv[1][0]);
                *(float4*)&h2[kl][4]     = make_float4(hv[2][0], hv[2][0], hv[3][0], hv[3][0]);
                *(float4*)&h2[kl + 1][0] = make_float4(hv[0][1], hv[0][1], hv[1][1], hv[1][1]);
                *(float4*)&h2[kl + 1][4] = make_float4(hv[2][1], hv[2][1], hv[3][1], hv[3][1]);
            }
            // coalesced h write for proj_out (t,b,k); fire-and-forget
            if (rank == 0) {
                #pragma unroll
                for (int r = 0; r < 4; ++r)
                    *(float2*)(g_H + ((size_t)t * 256 + b0 + r) * 256 + c)
                        = make_float2(hv[r][0], hv[r][1]);
            }
        }
        __syncthreads();
    }
}

// ---------------------------------------------------------------------------
// Kernel C: out[b,t,n] = gelu( sum_k H[t,b,k] * W_ho[n,k] + b_ho[n] )
// A rows are contiguous (t,b) with k-major layout. R4-style 128x64 tile.
// ---------------------------------------------------------------------------
__global__ void __launch_bounds__(256) proj_out_kernel(
    const float* __restrict__ W_ho, const float* __restrict__ b_ho,
    float* __restrict__ out)
{
    __shared__ float As[16][132];
    __shared__ float Bs[16][68];
    const int tid = threadIdx.x;
    const int r0  = blockIdx.x * 128;
    const int n0  = blockIdx.y * 64;
    const int t   = r0 >> 8;
    const int b0  = r0 & 255;
    const int tx  = tid & 15, ty = tid >> 4;

    float acc[8][4];
    #pragma unroll
    for (int i = 0; i < 8; ++i)
        #pragma unroll
        for (int j = 0; j < 4; ++j) acc[i][j] = 0.f;

    const int kq = (tid & 3) * 4;
    const int am = tid >> 2;

    for (int k0 = 0; k0 < H_SZ; k0 += 16) {
        #pragma unroll
        for (int h = 0; h < 2; ++h) {
            const int m = am + h * 64;
            const float4 v = *(const float4*)(g_H + (size_t)(r0 + m) * 256 + k0 + kq);
            As[kq + 0][m] = v.x; As[kq + 1][m] = v.y;
            As[kq + 2][m] = v.z; As[kq + 3][m] = v.w;
        }
        {
            const float4 v = *(const float4*)(W_ho + (size_t)(n0 + am) * H_SZ + k0 + kq);
            Bs[kq + 0][am] = v.x; Bs[kq + 1][am] = v.y;
            Bs[kq + 2][am] = v.z; Bs[kq + 3][am] = v.w;
        }
        __syncthreads();
        #pragma unroll
        for (int kk = 0; kk < 16; ++kk) {
            const float4 a0 = *(const float4*)&As[kk][ty * 8];
            const float4 a1 = *(const float4*)&As[kk][ty * 8 + 4];
            const float4 bv = *(const float4*)&Bs[kk][tx * 4];
            const float a[8] = {a0.x, a0.y, a0.z, a0.w, a1.x, a1.y, a1.z, a1.w};
            const float bb[4] = {bv.x, bv.y, bv.z, bv.w};
            #pragma unroll
            for (int i = 0; i < 8; ++i)
                #pragma unroll
                for (int j = 0; j < 4; ++j) acc[i][j] = fmaf(a[i], bb[j], acc[i][j]);
        }
        __syncthreads();
    }
    const float4 bv = *(const float4*)(b_ho + n0 + tx * 4);
    #pragma unroll
    for (int i = 0; i < 8; ++i) {
        float4 o;
        o.x = gelu_f(acc[i][0] + bv.x);
        o.y = gelu_f(acc[i][1] + bv.y);
        o.z = gelu_f(acc[i][2] + bv.z);
        o.w = gelu_f(acc[i][3] + bv.w);
        *(float4*)(out + (size_t)(b0 + ty * 8 + i) * (S_LEN * NO)
                   + (size_t)t * NO + n0 + tx * 4) = o;
    }
}

// ---------------------------------------------------------------------------
extern "C" void kernel_launch(void* const* d_in, const int* in_sizes, int n_in,
                              void* d_out, int out_size)
{
    const float* X     = (const float*)d_in[0];
    const float* W_ih  = (const float*)d_in[1];
    const float* b_ih  = (const float*)d_in[2];
    const float* W_ho  = (const float*)d_in[3];
    const float* b_ho  = (const float*)d_in[4];
    const float* gamma = (const float*)d_in[5];
    const float* beta  = (const float*)d_in[6];
    float* out = (float*)d_out;

    init_kernel<<<256, 256>>>();
    proj_in_kernel<<<dim3((S_LEN * B_SZ) / 128, H_SZ / 64), 256>>>(X, W_ih, b_ih);
    rec_kernel<<<128, 256>>>(W_ih, gamma, beta);
    proj_out_kernel<<<dim3((S_LEN * B_SZ) / 128, NO / 64), 256>>>(W_ho, b_ho, out);
}